// round 8
// baseline (speedup 1.0000x reference)
#include <cuda_runtime.h>

// Problem constants (fixed for this dataset)
#define BB   4
#define CC   128
#define HH   128
#define WW   128
#define GG   4
#define GCH  32      // channels per group
#define PP   9       // K*K taps
#define NOFF 72      // G*P*2
#define NMSK 36      // G*P
#define TILE 32      // pixels per block
#define NTHR 256
#define ROW  36      // xsT row length in floats (32 px + 4 pad, 16B-aligned)

// Union buffer layout:
//  Phase A (0..2): xsT[CC][ROW] @0 (18432 B) | offs[TILE][NOFF] @18432 (9216 B)
//                  | msk[TILE][NMSK] @27648 (4608 B)      -> 32256 B total
//  Phase B (2.5..3): swt[TILE][NMSK] float4 @0 (18432 B) | slin[TILE][NMSK] int
//                  @18432 (4608 B)                        -> 23040 B
// Phase 2.5 reads A into registers, __syncthreads, then writes B.
#define XST_OFF   0
#define OFFS_OFF  18432
#define MSK_OFF   27648
#define SLIN_OFF  18432
#define UBUF_BYTES 32256   // 31.5 KB

__global__ __launch_bounds__(NTHR, 6) void dcnv3_fused(
    const float* __restrict__ in,     // (B,H,W,C) channel-last (view of (B,C,H,W))
    const float* __restrict__ Woff,   // (C, 72) row-major
    const float* __restrict__ boff,   // (72)
    const float* __restrict__ Wmask,  // (C, 36) row-major
    const float* __restrict__ bmask,  // (36)
    float* __restrict__ out)          // (B,H,W,C) channel-last
{
    __shared__ __align__(16) char ubuf[UBUF_BYTES];

    float* xsT           = reinterpret_cast<float*>(ubuf + XST_OFF);   // [CC][ROW]
    float (*offs)[NOFF]  = reinterpret_cast<float(*)[NOFF]>(ubuf + OFFS_OFF);
    float (*msk)[NMSK]   = reinterpret_cast<float(*)[NMSK]>(ubuf + MSK_OFF);
    float4 (*swt)[NMSK]  = reinterpret_cast<float4(*)[NMSK]>(ubuf);
    int (*slin)[NMSK]    = reinterpret_cast<int(*)[NMSK]>(ubuf + SLIN_OFF);

    const int tid = threadIdx.x;
    const int blk = blockIdx.x;
    const int wt = blk % (WW / TILE);
    const int h  = (blk / (WW / TILE)) % HH;
    const int b  = blk / ((WW / TILE) * HH);
    const int w0 = wt * TILE;

    // ---- phase 0: load 32 pixels' features and store TRANSPOSED into xsT ----
    // lane groups of 4 do a 4x4 register transpose so STS.128 is conflict-free.
    const float4* xbase4 = reinterpret_cast<const float4*>(
        in + (((size_t)b * HH + h) * WW + w0) * CC);
    const int r = tid & 3;   // element/row index inside 4-lane transpose group
    #pragma unroll
    for (int it = 0; it < 4; it++) {
        const int i  = tid + it * NTHR;      // 0..1023
        const int q  = i >> 7;               // pixel quad 0..7
        const int k4 = (i >> 2) & 31;        // channel quad 0..31
        // load: pixel (4q + r), channels 4k4..4k4+3
        float4 v = xbase4[(q * 4 + r) * (CC / 4) + k4];
        float a0 = v.x, a1 = v.y, a2 = v.z, a3 = v.w;
        // 4x4 transpose across lanes (xor 1 then xor 2)
        {
            float s0 = (r & 1) ? a0 : a1;
            float s1 = (r & 1) ? a2 : a3;
            float g0 = __shfl_xor_sync(0xFFFFFFFF, s0, 1);
            float g1 = __shfl_xor_sync(0xFFFFFFFF, s1, 1);
            if (r & 1) { a0 = g0; a2 = g1; } else { a1 = g0; a3 = g1; }
        }
        {
            float u0 = (r & 2) ? a0 : a2;
            float u1 = (r & 2) ? a1 : a3;
            float h0 = __shfl_xor_sync(0xFFFFFFFF, u0, 2);
            float h1 = __shfl_xor_sync(0xFFFFFFFF, u1, 2);
            if (r & 2) { a0 = h0; a1 = h1; } else { a2 = h0; a3 = h1; }
        }
        // now lane holds channel (4*k4 + r) for pixels 4q..4q+3
        *reinterpret_cast<float4*>(&xsT[(4 * k4 + r) * ROW + 4 * q]) =
            make_float4(a0, a1, a2, a3);
    }
    __syncthreads();

    // ---- phase 1: register-tiled matvec. 4 pixels x 4 outputs per thread.
    // jq = tid>>3 (27 j-quads), pg = tid&7 (8 pixel quads).
    // W LDG.128: 4 adjacent j-quads per warp -> ~1 wavefront (broadcast).
    // x LDS.128: 8 pixel quads cover 128 contiguous bytes -> conflict-free.
    if (tid < 216) {
        const int jq = tid >> 3;             // 0..26
        const int pg = tid & 7;              // 0..7
        const int p0 = pg * 4;
        const bool is_off = (jq < 18);
        const int j0 = is_off ? jq * 4 : (jq - 18) * 4;
        const float* Wb = (is_off ? Woff : Wmask) + j0;
        const int ws = is_off ? NOFF : NMSK;     // row stride in floats
        const float* bias = is_off ? boff : bmask;

        float4 acc0 = make_float4(0.f, 0.f, 0.f, 0.f);
        float4 acc1 = make_float4(0.f, 0.f, 0.f, 0.f);
        float4 acc2 = make_float4(0.f, 0.f, 0.f, 0.f);
        float4 acc3 = make_float4(0.f, 0.f, 0.f, 0.f);

        #pragma unroll 4
        for (int k = 0; k < CC; k++) {
            const float4 xq = *reinterpret_cast<const float4*>(&xsT[k * ROW + p0]);
            const float4 w  = *reinterpret_cast<const float4*>(&Wb[k * ws]);
            acc0.x = fmaf(xq.x, w.x, acc0.x);
            acc0.y = fmaf(xq.x, w.y, acc0.y);
            acc0.z = fmaf(xq.x, w.z, acc0.z);
            acc0.w = fmaf(xq.x, w.w, acc0.w);
            acc1.x = fmaf(xq.y, w.x, acc1.x);
            acc1.y = fmaf(xq.y, w.y, acc1.y);
            acc1.z = fmaf(xq.y, w.z, acc1.z);
            acc1.w = fmaf(xq.y, w.w, acc1.w);
            acc2.x = fmaf(xq.z, w.x, acc2.x);
            acc2.y = fmaf(xq.z, w.y, acc2.y);
            acc2.z = fmaf(xq.z, w.z, acc2.z);
            acc2.w = fmaf(xq.z, w.w, acc2.w);
            acc3.x = fmaf(xq.w, w.x, acc3.x);
            acc3.y = fmaf(xq.w, w.y, acc3.y);
            acc3.z = fmaf(xq.w, w.z, acc3.z);
            acc3.w = fmaf(xq.w, w.w, acc3.w);
        }
        const float4 bv = *reinterpret_cast<const float4*>(bias + j0);
        acc0.x += bv.x; acc0.y += bv.y; acc0.z += bv.z; acc0.w += bv.w;
        acc1.x += bv.x; acc1.y += bv.y; acc1.z += bv.z; acc1.w += bv.w;
        acc2.x += bv.x; acc2.y += bv.y; acc2.z += bv.z; acc2.w += bv.w;
        acc3.x += bv.x; acc3.y += bv.y; acc3.z += bv.z; acc3.w += bv.w;

        if (is_off) {
            *reinterpret_cast<float4*>(&offs[p0 + 0][j0]) = acc0;
            *reinterpret_cast<float4*>(&offs[p0 + 1][j0]) = acc1;
            *reinterpret_cast<float4*>(&offs[p0 + 2][j0]) = acc2;
            *reinterpret_cast<float4*>(&offs[p0 + 3][j0]) = acc3;
        } else {
            *reinterpret_cast<float4*>(&msk[p0 + 0][j0]) = acc0;
            *reinterpret_cast<float4*>(&msk[p0 + 1][j0]) = acc1;
            *reinterpret_cast<float4*>(&msk[p0 + 2][j0]) = acc2;
            *reinterpret_cast<float4*>(&msk[p0 + 3][j0]) = acc3;
        }
    }
    __syncthreads();

    // ---- phase 2: softmax over the 9 taps per (pixel, group) ----
    if (tid < TILE * GG) {
        const int pp = tid / GG, g = tid % GG;
        float* m = &msk[pp][g * PP];
        float mx = m[0];
        #pragma unroll
        for (int p = 1; p < PP; p++) mx = fmaxf(mx, m[p]);
        float e[PP], s = 0.f;
        #pragma unroll
        for (int p = 0; p < PP; p++) { e[p] = __expf(m[p] - mx); s += e[p]; }
        const float inv = 1.f / s;
        #pragma unroll
        for (int p = 0; p < PP; p++) m[p] = e[p] * inv;
    }
    __syncthreads();

    // ---- phase 2.5: read offs/msk -> registers, sync, write swt/slin over them.
    // 1152 items, 256 threads -> <=5 items/thread buffered in registers.
    {
        float rw[5][4];
        int   rl[5];
        #pragma unroll
        for (int k = 0; k < 5; k++) {
            const int idx = tid + k * NTHR;
            if (idx < TILE * NMSK) {
                const int pp = idx / NMSK;
                const int gp = idx % NMSK;
                const int p  = gp % PP;
                const float dx = offs[pp][gp * 2 + 0];
                const float dy = offs[pp][gp * 2 + 1];
                // padded coords: px = w + p/3 + dx ; py = h + p%3 + dy
                const float px = (float)(w0 + pp) + (float)(p / 3) + dx;
                const float py = (float)h + (float)(p % 3) + dy;
                const float x0f = floorf(px), y0f = floorf(py);
                const float tx = px - x0f, ty = py - y0f;
                const int ix0 = (int)x0f, iy0 = (int)y0f;
                const float m = msk[pp][gp];

                float w00 = (1.f - tx) * (1.f - ty) * m;
                float w10 = tx * (1.f - ty) * m;
                float w01 = (1.f - tx) * ty * m;
                float w11 = tx * ty * m;
                // zero out-of-range corners (padded coord must be in [1,128])
                const bool vx0 = ((unsigned)(ix0 - 1) < (unsigned)WW);
                const bool vx1 = ((unsigned)(ix0)     < (unsigned)WW);
                const bool vy0 = ((unsigned)(iy0 - 1) < (unsigned)HH);
                const bool vy1 = ((unsigned)(iy0)     < (unsigned)HH);
                if (!(vx0 && vy0)) w00 = 0.f;
                if (!(vx1 && vy0)) w10 = 0.f;
                if (!(vx0 && vy1)) w01 = 0.f;
                if (!(vx1 && vy1)) w11 = 0.f;

                rw[k][0] = w00; rw[k][1] = w10; rw[k][2] = w01; rw[k][3] = w11;
                rl[k] = ((b * HH + (iy0 - 1)) * WW + (ix0 - 1)) * CC;
            }
        }
        __syncthreads();   // all reads of offs/msk complete before overwrite
        #pragma unroll
        for (int k = 0; k < 5; k++) {
            const int idx = tid + k * NTHR;
            if (idx < TILE * NMSK) {
                const int pp = idx / NMSK;
                const int gp = idx % NMSK;
                swt[pp][gp]  = make_float4(rw[k][0], rw[k][1], rw[k][2], rw[k][3]);
                slin[pp][gp] = rl[k];
            }
        }
    }
    __syncthreads();

    // ---- phase 3: BRANCHLESS gather. warp = pixel, lane = float4 channel slot.
    const int c4 = tid & 31;          // float4 slot -> channels [4*c4, 4*c4+3]
    const int g  = c4 >> 3;           // group of this channel slot
    const float4* in4 = reinterpret_cast<const float4*>(in);
    float4* out4 = reinterpret_cast<float4*>(out);

    #pragma unroll
    for (int pass = 0; pass < 4; pass++) {
        const int pp = (tid >> 5) + pass * 8;
        float4 acc = make_float4(0.f, 0.f, 0.f, 0.f);
        #pragma unroll
        for (int p = 0; p < PP; p++) {
            const int gp = g * PP + p;
            const float4 wv = swt[pp][gp];
            const int base = (slin[pp][gp] >> 2) + c4;   // float4 units
            const int a00 = (wv.x != 0.f) ? base : 0;
            const int a10 = (wv.y != 0.f) ? base + (CC / 4) : 0;
            const int a01 = (wv.z != 0.f) ? base + (WW * CC / 4) : 0;
            const int a11 = (wv.w != 0.f) ? base + (WW * CC / 4) + (CC / 4) : 0;
            const float4 v00 = in4[a00];
            const float4 v10 = in4[a10];
            const float4 v01 = in4[a01];
            const float4 v11 = in4[a11];
            acc.x = fmaf(wv.x, v00.x, acc.x); acc.y = fmaf(wv.x, v00.y, acc.y);
            acc.z = fmaf(wv.x, v00.z, acc.z); acc.w = fmaf(wv.x, v00.w, acc.w);
            acc.x = fmaf(wv.y, v10.x, acc.x); acc.y = fmaf(wv.y, v10.y, acc.y);
            acc.z = fmaf(wv.y, v10.z, acc.z); acc.w = fmaf(wv.y, v10.w, acc.w);
            acc.x = fmaf(wv.z, v01.x, acc.x); acc.y = fmaf(wv.z, v01.y, acc.y);
            acc.z = fmaf(wv.z, v01.z, acc.z); acc.w = fmaf(wv.z, v01.w, acc.w);
            acc.x = fmaf(wv.w, v11.x, acc.x); acc.y = fmaf(wv.w, v11.y, acc.y);
            acc.z = fmaf(wv.w, v11.z, acc.z); acc.w = fmaf(wv.w, v11.w, acc.w);
        }
        const size_t o = (((size_t)b * HH + h) * WW + (w0 + pp)) * (CC / 4) + c4;
        out4[o] = acc;
    }
}

extern "C" void kernel_launch(void* const* d_in, const int* in_sizes, int n_in,
                              void* d_out, int out_size) {
    const float* inp   = (const float*)d_in[0];
    const float* Woff  = (const float*)d_in[1];
    const float* boff  = (const float*)d_in[2];
    const float* Wmask = (const float*)d_in[3];
    const float* bmask = (const float*)d_in[4];
    float* out = (float*)d_out;

    const int nblocks = BB * HH * (WW / TILE);   // 4*128*4 = 2048
    dcnv3_fused<<<nblocks, NTHR>>>(inp, Woff, boff, Wmask, bmask, out);
}

// round 9
// speedup vs baseline: 1.2060x; 1.2060x over previous
#include <cuda_runtime.h>
#include <cuda_fp16.h>

// Problem constants (fixed for this dataset)
#define BB   4
#define CC   128
#define HH   128
#define WW   128
#define GG   4
#define PP   9       // K*K taps
#define NOFF 72      // G*P*2
#define NMSK 36      // G*P
#define TILE 32      // pixels per block
#define NTHR 256
#define ROW  36      // xsT row length in floats (32 px + 4 pad, 16B-aligned)
#define SP   132     // padded scratch dim (img+pad); entry (b,g,yp,xp)

// fp16 pair-gather scratch: entry (b,g,yp,xp) = 128B =
//   [64B: ch0-31 of img col (xp-1), row (yp-1)] [64B: ch0-31 of img col xp]
// zero outside the image. 278784 entries * 128B = 35.7 MB.
#define NENT (BB * GG * SP * SP)
__device__ uint4 xh_scratch[NENT * 8];

// overlay buffer: phases 0/1 use it as xsT[CC][ROW] (18432 B);
// phases 2.5/3 use it as swt[TILE][NMSK] float4 (18432 B) + sent[TILE][NMSK] int
#define UBUF_BYTES (TILE * NMSK * 16 + TILE * NMSK * 4)   // 23040

// ---------------- conversion kernel: fp32 (B,H,W,C) -> fp16 pair scratch ----
__global__ __launch_bounds__(256) void conv_fp16(const float* __restrict__ in) {
    const int t = blockIdx.x * 256 + threadIdx.x;
    if (t >= NENT * 8) return;
    const int part = t & 7;          // 16B slice within the 128B entry
    const int e    = t >> 3;
    const int xp = e % SP;
    const int yp = (e / SP) % SP;
    const int g  = (e / (SP * SP)) % GG;
    const int b  =  e / (SP * SP * GG);
    const int col = xp - 1 + (part >> 2);   // part<4: left col, part>=4: right
    const int row = yp - 1;
    const int ch0 = (part & 3) * 8;
    uint4 v = make_uint4(0u, 0u, 0u, 0u);
    if ((unsigned)row < (unsigned)HH && (unsigned)col < (unsigned)WW) {
        const float4* s = reinterpret_cast<const float4*>(
            in + (((size_t)b * HH + row) * WW + col) * CC + g * 32 + ch0);
        const float4 f0 = s[0];
        const float4 f1 = s[1];
        __half2 h0 = __floats2half2_rn(f0.x, f0.y);
        __half2 h1 = __floats2half2_rn(f0.z, f0.w);
        __half2 h2 = __floats2half2_rn(f1.x, f1.y);
        __half2 h3 = __floats2half2_rn(f1.z, f1.w);
        v.x = *reinterpret_cast<unsigned int*>(&h0);
        v.y = *reinterpret_cast<unsigned int*>(&h1);
        v.z = *reinterpret_cast<unsigned int*>(&h2);
        v.w = *reinterpret_cast<unsigned int*>(&h3);
    }
    xh_scratch[t] = v;
}

// ---------------- main fused kernel ----------------------------------------
__global__ __launch_bounds__(NTHR, 5) void dcnv3_fused(
    const float* __restrict__ in,     // (B,H,W,C) channel-last
    const float* __restrict__ Woff,   // (C, 72) row-major
    const float* __restrict__ boff,   // (72)
    const float* __restrict__ Wmask,  // (C, 36) row-major
    const float* __restrict__ bmask,  // (36)
    float* __restrict__ out)          // (B,H,W,C) channel-last
{
    __shared__ __align__(16) char ubuf[UBUF_BYTES];   // 22.5 KB (xsT | swt+sent)
    __shared__ float offs[TILE][NOFF];                // 9 KB
    __shared__ float msk[TILE][NMSK];                 // 4.5 KB

    float* xsT           = reinterpret_cast<float*>(ubuf);             // [CC][ROW]
    float4 (*swt)[NMSK]  = reinterpret_cast<float4(*)[NMSK]>(ubuf);
    int (*sent)[NMSK]    = reinterpret_cast<int(*)[NMSK]>(ubuf + TILE * NMSK * 16);

    const int tid = threadIdx.x;
    const int blk = blockIdx.x;
    const int wt = blk % (WW / TILE);
    const int h  = (blk / (WW / TILE)) % HH;
    const int b  = blk / ((WW / TILE) * HH);
    const int w0 = wt * TILE;

    // ---- phase 0: load 32 pixels' features TRANSPOSED into xsT (fp32) ----
    const float4* xbase4 = reinterpret_cast<const float4*>(
        in + (((size_t)b * HH + h) * WW + w0) * CC);
    const int r = tid & 3;
    #pragma unroll
    for (int it = 0; it < 4; it++) {
        const int i  = tid + it * NTHR;      // 0..1023
        const int q  = i >> 7;               // pixel quad 0..7
        const int k4 = (i >> 2) & 31;        // channel quad 0..31
        float4 v = xbase4[(q * 4 + r) * (CC / 4) + k4];
        float a0 = v.x, a1 = v.y, a2 = v.z, a3 = v.w;
        {
            float s0 = (r & 1) ? a0 : a1;
            float s1 = (r & 1) ? a2 : a3;
            float g0 = __shfl_xor_sync(0xFFFFFFFF, s0, 1);
            float g1 = __shfl_xor_sync(0xFFFFFFFF, s1, 1);
            if (r & 1) { a0 = g0; a2 = g1; } else { a1 = g0; a3 = g1; }
        }
        {
            float u0 = (r & 2) ? a0 : a2;
            float u1 = (r & 2) ? a1 : a3;
            float h0 = __shfl_xor_sync(0xFFFFFFFF, u0, 2);
            float h1 = __shfl_xor_sync(0xFFFFFFFF, u1, 2);
            if (r & 2) { a0 = h0; a1 = h1; } else { a2 = h0; a3 = h1; }
        }
        *reinterpret_cast<float4*>(&xsT[(4 * k4 + r) * ROW + 4 * q]) =
            make_float4(a0, a1, a2, a3);
    }
    __syncthreads();

    // ---- phase 1: register-tiled matvec (fp32, unchanged) ----
    if (tid < 216) {
        const int jq = tid >> 3;             // 0..26
        const int pg = tid & 7;              // 0..7
        const int p0 = pg * 4;
        const bool is_off = (jq < 18);
        const int j0 = is_off ? jq * 4 : (jq - 18) * 4;
        const float* Wb = (is_off ? Woff : Wmask) + j0;
        const int ws = is_off ? NOFF : NMSK;
        const float* bias = is_off ? boff : bmask;

        float4 acc0 = make_float4(0.f, 0.f, 0.f, 0.f);
        float4 acc1 = make_float4(0.f, 0.f, 0.f, 0.f);
        float4 acc2 = make_float4(0.f, 0.f, 0.f, 0.f);
        float4 acc3 = make_float4(0.f, 0.f, 0.f, 0.f);

        #pragma unroll 4
        for (int k = 0; k < CC; k++) {
            const float4 xq = *reinterpret_cast<const float4*>(&xsT[k * ROW + p0]);
            const float4 w  = *reinterpret_cast<const float4*>(&Wb[k * ws]);
            acc0.x = fmaf(xq.x, w.x, acc0.x);
            acc0.y = fmaf(xq.x, w.y, acc0.y);
            acc0.z = fmaf(xq.x, w.z, acc0.z);
            acc0.w = fmaf(xq.x, w.w, acc0.w);
            acc1.x = fmaf(xq.y, w.x, acc1.x);
            acc1.y = fmaf(xq.y, w.y, acc1.y);
            acc1.z = fmaf(xq.y, w.z, acc1.z);
            acc1.w = fmaf(xq.y, w.w, acc1.w);
            acc2.x = fmaf(xq.z, w.x, acc2.x);
            acc2.y = fmaf(xq.z, w.y, acc2.y);
            acc2.z = fmaf(xq.z, w.z, acc2.z);
            acc2.w = fmaf(xq.z, w.w, acc2.w);
            acc3.x = fmaf(xq.w, w.x, acc3.x);
            acc3.y = fmaf(xq.w, w.y, acc3.y);
            acc3.z = fmaf(xq.w, w.z, acc3.z);
            acc3.w = fmaf(xq.w, w.w, acc3.w);
        }
        const float4 bv = *reinterpret_cast<const float4*>(bias + j0);
        acc0.x += bv.x; acc0.y += bv.y; acc0.z += bv.z; acc0.w += bv.w;
        acc1.x += bv.x; acc1.y += bv.y; acc1.z += bv.z; acc1.w += bv.w;
        acc2.x += bv.x; acc2.y += bv.y; acc2.z += bv.z; acc2.w += bv.w;
        acc3.x += bv.x; acc3.y += bv.y; acc3.z += bv.z; acc3.w += bv.w;

        if (is_off) {
            *reinterpret_cast<float4*>(&offs[p0 + 0][j0]) = acc0;
            *reinterpret_cast<float4*>(&offs[p0 + 1][j0]) = acc1;
            *reinterpret_cast<float4*>(&offs[p0 + 2][j0]) = acc2;
            *reinterpret_cast<float4*>(&offs[p0 + 3][j0]) = acc3;
        } else {
            *reinterpret_cast<float4*>(&msk[p0 + 0][j0]) = acc0;
            *reinterpret_cast<float4*>(&msk[p0 + 1][j0]) = acc1;
            *reinterpret_cast<float4*>(&msk[p0 + 2][j0]) = acc2;
            *reinterpret_cast<float4*>(&msk[p0 + 3][j0]) = acc3;
        }
    }
    __syncthreads();

    // ---- phase 2: softmax over the 9 taps per (pixel, group) ----
    if (tid < TILE * GG) {
        const int pp = tid / GG, g = tid % GG;
        float* m = &msk[pp][g * PP];
        float mx = m[0];
        #pragma unroll
        for (int p = 1; p < PP; p++) mx = fmaxf(mx, m[p]);
        float e[PP], s = 0.f;
        #pragma unroll
        for (int p = 0; p < PP; p++) { e[p] = __expf(m[p] - mx); s += e[p]; }
        const float inv = 1.f / s;
        #pragma unroll
        for (int p = 0; p < PP; p++) m[p] = e[p] * inv;
    }
    __syncthreads();

    // ---- phase 2.5: mask-folded corner weights + scratch ENTRY index ----
    // (overwrites xsT; safe — xsT dead after phase 1)
    for (int idx = tid; idx < TILE * NMSK; idx += NTHR) {
        const int pp = idx / NMSK;
        const int gp = idx % NMSK;
        const int g  = gp / PP;
        const int p  = gp % PP;
        const float dx = offs[pp][gp * 2 + 0];
        const float dy = offs[pp][gp * 2 + 1];
        const float px = (float)(w0 + pp) + (float)(p / 3) + dx;   // padded coords
        const float py = (float)h + (float)(p % 3) + dy;
        const float x0f = floorf(px), y0f = floorf(py);
        const float tx = px - x0f, ty = py - y0f;
        const int ix0 = (int)x0f, iy0 = (int)y0f;
        const float m = msk[pp][gp];

        float w00 = (1.f - tx) * (1.f - ty) * m;
        float w10 = tx * (1.f - ty) * m;
        float w01 = (1.f - tx) * ty * m;
        float w11 = tx * ty * m;
        // zero weights of out-of-range corners (img coord = padded-1)
        const bool vx0 = ((unsigned)(ix0 - 1) < (unsigned)WW);
        const bool vx1 = ((unsigned)(ix0)     < (unsigned)WW);
        const bool vy0 = ((unsigned)(iy0 - 1) < (unsigned)HH);
        const bool vy1 = ((unsigned)(iy0)     < (unsigned)HH);
        if (!(vx0 && vy0)) w00 = 0.f;
        if (!(vx1 && vy0)) w10 = 0.f;
        if (!(vx0 && vy1)) w01 = 0.f;
        if (!(vx1 && vy1)) w11 = 0.f;

        swt[pp][gp] = make_float4(w00, w10, w01, w11);
        // scratch entry (b,g, yp=iy0, xp=ix0): covers img cols (ix0-1, ix0),
        // row img iy0-1; row+1 entry = +SP.  Clamp to entry 0 when the index
        // would leave the padded array (weights are all zero in that case).
        const bool ok = ((unsigned)ix0 <= 130u) && ((unsigned)iy0 <= 130u);
        sent[pp][gp] = ok ? (((b * GG + g) * SP + iy0) * SP + ix0) : 0;
    }
    __syncthreads();

    // ---- phase 3: fp16 pair gather.  warp = pixel; lane = (g, sub) where
    // sub = 16B slice of the 128B entry: sub>>2 = corner half (x0/x1),
    // sub&3 = channel octet.  Two 128B row loads per tap (y0,y1). ----
    const int lane = tid & 31;
    const int g3   = lane >> 3;
    const int sub  = lane & 7;
    const int cr   = sub >> 2;          // 0: left corner col, 1: right

    #pragma unroll
    for (int pass = 0; pass < 4; pass++) {
        const int pp = (tid >> 5) + pass * 8;
        float acc[8];
        #pragma unroll
        for (int i = 0; i < 8; i++) acc[i] = 0.f;

        #pragma unroll
        for (int p = 0; p < PP; p++) {
            const int gp = g3 * PP + p;
            const float* wp = reinterpret_cast<const float*>(&swt[pp][gp]);
            const float wr0 = wp[cr];       // row y0: w00 / w10
            const float wr1 = wp[2 + cr];   // row y1: w01 / w11
            const int e = sent[pp][gp];
            const uint4 d0 = xh_scratch[e * 8 + sub];
            const uint4 d1 = xh_scratch[(e + SP) * 8 + sub];
            float2 f;
            f = __half22float2(*reinterpret_cast<const __half2*>(&d0.x));
            acc[0] = fmaf(wr0, f.x, acc[0]); acc[1] = fmaf(wr0, f.y, acc[1]);
            f = __half22float2(*reinterpret_cast<const __half2*>(&d0.y));
            acc[2] = fmaf(wr0, f.x, acc[2]); acc[3] = fmaf(wr0, f.y, acc[3]);
            f = __half22float2(*reinterpret_cast<const __half2*>(&d0.z));
            acc[4] = fmaf(wr0, f.x, acc[4]); acc[5] = fmaf(wr0, f.y, acc[5]);
            f = __half22float2(*reinterpret_cast<const __half2*>(&d0.w));
            acc[6] = fmaf(wr0, f.x, acc[6]); acc[7] = fmaf(wr0, f.y, acc[7]);
            f = __half22float2(*reinterpret_cast<const __half2*>(&d1.x));
            acc[0] = fmaf(wr1, f.x, acc[0]); acc[1] = fmaf(wr1, f.y, acc[1]);
            f = __half22float2(*reinterpret_cast<const __half2*>(&d1.y));
            acc[2] = fmaf(wr1, f.x, acc[2]); acc[3] = fmaf(wr1, f.y, acc[3]);
            f = __half22float2(*reinterpret_cast<const __half2*>(&d1.z));
            acc[4] = fmaf(wr1, f.x, acc[4]); acc[5] = fmaf(wr1, f.y, acc[5]);
            f = __half22float2(*reinterpret_cast<const __half2*>(&d1.w));
            acc[6] = fmaf(wr1, f.x, acc[6]); acc[7] = fmaf(wr1, f.y, acc[7]);
        }
        // combine left/right corner partials (lane ^ 4)
        #pragma unroll
        for (int i = 0; i < 8; i++)
            acc[i] += __shfl_xor_sync(0xFFFFFFFF, acc[i], 4);

        if (!(lane & 4)) {      // sub in 0..3 -> channel octet
            float* op = out + (((size_t)b * HH + h) * WW + (w0 + pp)) * CC
                            + g3 * 32 + sub * 8;
            *reinterpret_cast<float4*>(op) =
                make_float4(acc[0], acc[1], acc[2], acc[3]);
            *reinterpret_cast<float4*>(op + 4) =
                make_float4(acc[4], acc[5], acc[6], acc[7]);
        }
    }
}

extern "C" void kernel_launch(void* const* d_in, const int* in_sizes, int n_in,
                              void* d_out, int out_size) {
    const float* inp   = (const float*)d_in[0];
    const float* Woff  = (const float*)d_in[1];
    const float* boff  = (const float*)d_in[2];
    const float* Wmask = (const float*)d_in[3];
    const float* bmask = (const float*)d_in[4];
    float* out = (float*)d_out;

    const int conv_blocks = (NENT * 8 + 255) / 256;     // 8712
    conv_fp16<<<conv_blocks, 256>>>(inp);

    const int nblocks = BB * HH * (WW / TILE);          // 2048
    dcnv3_fused<<<nblocks, NTHR>>>(inp, Woff, boff, Wmask, bmask, out);
}